// round 1
// baseline (speedup 1.0000x reference)
#include <cuda_runtime.h>

#define BB 4
#define SS 2048
#define EE 1024
#define HH 16
#define DD 64
#define QQ 4
#define MM (BB*SS)   /* 8192 tokens */

// Scratch (allocation-free rule: __device__ globals)
__device__ float g_q[(size_t)MM * (QQ*EE)];  // [n][q*E+f]   134 MB
__device__ float g_k[(size_t)MM * EE];       // [n][f]
__device__ float g_v[(size_t)MM * EE];
__device__ float g_z[(size_t)MM * EE];       // shuffled, pre-sum attn output

// C[M,N] = A[M,K] @ W[N,K]^T + bias[N]; all row-major, K-contiguous.
// BM=BN=128, BK=16, 256 threads, 8x8 per thread.
__global__ __launch_bounds__(256) void sgemm_bias(
    const float* __restrict__ A, const float* __restrict__ W,
    const float* __restrict__ bias, float* __restrict__ C,
    int M, int N, int K)
{
    const int BM = 128, BN = 128, BK = 16;
    __shared__ float As[BK][BM + 4];
    __shared__ float Ws[BK][BN + 4];

    const int tid = threadIdx.x;
    const int m0 = blockIdx.y * BM;
    const int n0 = blockIdx.x * BN;
    const int tx = tid & 15;       // col group
    const int ty = tid >> 4;       // row group

    float acc[8][8];
    #pragma unroll
    for (int i = 0; i < 8; i++)
        #pragma unroll
        for (int j = 0; j < 8; j++) acc[i][j] = 0.f;

    for (int kt = 0; kt < K; kt += BK) {
        // Load tiles: 512 float4s per operand, 2 per thread, stored transposed.
        #pragma unroll
        for (int t = 0; t < 2; t++) {
            int f   = tid * 2 + t;
            int row = f >> 2;
            int seg = (f & 3) * 4;
            float4 av = *(const float4*)(A + (size_t)(m0 + row) * K + kt + seg);
            As[seg + 0][row] = av.x; As[seg + 1][row] = av.y;
            As[seg + 2][row] = av.z; As[seg + 3][row] = av.w;
            float4 wv = *(const float4*)(W + (size_t)(n0 + row) * K + kt + seg);
            Ws[seg + 0][row] = wv.x; Ws[seg + 1][row] = wv.y;
            Ws[seg + 2][row] = wv.z; Ws[seg + 3][row] = wv.w;
        }
        __syncthreads();

        #pragma unroll
        for (int k = 0; k < BK; k++) {
            float4 a0 = *(const float4*)&As[k][ty * 8];
            float4 a1 = *(const float4*)&As[k][ty * 8 + 4];
            float4 w0 = *(const float4*)&Ws[k][tx * 8];
            float4 w1 = *(const float4*)&Ws[k][tx * 8 + 4];
            float a[8] = {a0.x, a0.y, a0.z, a0.w, a1.x, a1.y, a1.z, a1.w};
            float w[8] = {w0.x, w0.y, w0.z, w0.w, w1.x, w1.y, w1.z, w1.w};
            #pragma unroll
            for (int i = 0; i < 8; i++)
                #pragma unroll
                for (int j = 0; j < 8; j++)
                    acc[i][j] += a[i] * w[j];
        }
        __syncthreads();
    }

    // Epilogue with bias
    float bv[8];
    #pragma unroll
    for (int j = 0; j < 8; j++) bv[j] = bias[n0 + tx * 8 + j];
    #pragma unroll
    for (int i = 0; i < 8; i++) {
        float* cp = C + (size_t)(m0 + ty * 8 + i) * N + n0 + tx * 8;
        float4 c0 = make_float4(acc[i][0] + bv[0], acc[i][1] + bv[1],
                                acc[i][2] + bv[2], acc[i][3] + bv[3]);
        float4 c1 = make_float4(acc[i][4] + bv[4], acc[i][5] + bv[5],
                                acc[i][6] + bv[6], acc[i][7] + bv[7]);
        *(float4*)(cp)     = c0;
        *(float4*)(cp + 4) = c1;
    }
}

// Per-token attention: scores over heads (16x16), softmax over g, P@V,
// summed over the 4 query projections, written directly into the shuffled
// layout Z[b, h*128 + sp/16, (sp%16)*64 + d].
__global__ __launch_bounds__(256) void attn_kernel(
    const float* __restrict__ qb, const float* __restrict__ kb,
    const float* __restrict__ vb, float* __restrict__ z)
{
    __shared__ float sk[HH][DD + 1];
    __shared__ float sv[HH][DD + 1];
    __shared__ float sq[HH][DD + 1];
    __shared__ float ss[HH][HH + 1];
    __shared__ float sp_[HH][HH + 1];

    const int n   = blockIdx.x;     // token id = b*S + sp
    const int b   = n >> 11;        // n / 2048
    const int sp  = n & 2047;
    const int tid = threadIdx.x;

    for (int i = tid; i < EE; i += 256) {
        sk[i >> 6][i & 63] = kb[(size_t)n * EE + i];
        sv[i >> 6][i & 63] = vb[(size_t)n * EE + i];
    }

    const int d  = tid & 63;       // this thread's head-dim slot (out phase)
    const int hq = tid >> 6;       // head group (4 heads per thread)
    const int sh = tid >> 4;       // score row h
    const int sg = tid & 15;       // score col g
    const float scale = 0.125f;    // 1/sqrt(64)

    float acc[4] = {0.f, 0.f, 0.f, 0.f};

    for (int qi = 0; qi < QQ; qi++) {
        for (int i = tid; i < EE; i += 256)
            sq[i >> 6][i & 63] = qb[(size_t)n * (QQ * EE) + qi * EE + i];
        __syncthreads();

        // scores[h][g] = scale * q[h]·k[g]
        float s = 0.f;
        #pragma unroll
        for (int dd = 0; dd < DD; dd++) s += sq[sh][dd] * sk[sg][dd];
        ss[sh][sg] = s * scale;
        __syncthreads();

        // softmax over g (rows handled by threads 0..15)
        if (tid < HH) {
            float m = -1e30f;
            #pragma unroll
            for (int g = 0; g < HH; g++) m = fmaxf(m, ss[tid][g]);
            float e[HH], sum = 0.f;
            #pragma unroll
            for (int g = 0; g < HH; g++) { e[g] = __expf(ss[tid][g] - m); sum += e[g]; }
            float inv = 1.f / sum;
            #pragma unroll
            for (int g = 0; g < HH; g++) sp_[tid][g] = e[g] * inv;
        }
        __syncthreads();

        // out[h][d] += P[h]·V[:,d], accumulated over qi
        #pragma unroll
        for (int j = 0; j < 4; j++) {
            int h = hq * 4 + j;
            float o = 0.f;
            #pragma unroll
            for (int g = 0; g < HH; g++) o += sp_[h][g] * sv[g][d];
            acc[j] += o;
        }
        __syncthreads();   // protect sq/ss/sp_ before next iteration's writes
    }

    // shuffled write: s_new = h*128 + sp/16 ; e = (sp%16)*64 + d
    #pragma unroll
    for (int j = 0; j < 4; j++) {
        int h    = hq * 4 + j;
        int sfin = h * 128 + (sp >> 4);
        int e    = ((sp & 15) << 6) + d;
        z[((size_t)b * SS + sfin) * EE + e] = acc[j];
    }
}

extern "C" void kernel_launch(void* const* d_in, const int* in_sizes, int n_in,
                              void* d_out, int out_size)
{
    const float* x  = (const float*)d_in[0];
    const float* Wq = (const float*)d_in[1];  // (Q,E,E) == flat (4096,1024)
    const float* bq = (const float*)d_in[2];  // flat 4096
    const float* Wk = (const float*)d_in[3];
    const float* bk = (const float*)d_in[4];
    const float* Wv = (const float*)d_in[5];
    const float* bv = (const float*)d_in[6];
    const float* Wo = (const float*)d_in[7];
    const float* bo = (const float*)d_in[8];
    float* out = (float*)d_out;

    float *pq, *pk, *pv, *pz;
    cudaGetSymbolAddress((void**)&pq, g_q);
    cudaGetSymbolAddress((void**)&pk, g_k);
    cudaGetSymbolAddress((void**)&pv, g_v);
    cudaGetSymbolAddress((void**)&pz, g_z);

    dim3 blk(256);
    // Q projection: all 4 query weights as one (4096,1024) GEMM
    sgemm_bias<<<dim3(QQ * EE / 128, MM / 128), blk>>>(x, Wq, bq, pq, MM, QQ * EE, EE);
    // K / V projections
    sgemm_bias<<<dim3(EE / 128, MM / 128), blk>>>(x, Wk, bk, pk, MM, EE, EE);
    sgemm_bias<<<dim3(EE / 128, MM / 128), blk>>>(x, Wv, bv, pv, MM, EE, EE);
    // attention + softmax + q-sum + shuffle
    attn_kernel<<<MM, blk>>>(pq, pk, pv, pz);
    // output projection straight into d_out
    sgemm_bias<<<dim3(EE / 128, MM / 128), blk>>>(pz, Wo, bo, out, MM, EE, EE);
}

// round 3
// speedup vs baseline: 2.0794x; 2.0794x over previous
#include <cuda_runtime.h>
#include <cuda_bf16.h>

typedef unsigned int u32;
typedef unsigned long long u64;

#define BB 4
#define SS 2048
#define EE 1024
#define HH 16
#define DD 64
#define QQ 4
#define MM (BB*SS)   /* 8192 tokens */

// ───────── scratch (allocation-free rule: __device__ globals) ─────────
__device__ float g_q[(size_t)MM * (QQ*EE)];
__device__ float g_k[(size_t)MM * EE];
__device__ float g_v[(size_t)MM * EE];
__device__ float g_z[(size_t)MM * EE];

__device__ __nv_bfloat16 g_xh[(size_t)MM*EE],  g_xl[(size_t)MM*EE];
__device__ __nv_bfloat16 g_zh[(size_t)MM*EE],  g_zl[(size_t)MM*EE];
__device__ __nv_bfloat16 g_wqh[(size_t)QQ*EE*EE], g_wql[(size_t)QQ*EE*EE];
__device__ __nv_bfloat16 g_wkh[(size_t)EE*EE], g_wkl[(size_t)EE*EE];
__device__ __nv_bfloat16 g_wvh[(size_t)EE*EE], g_wvl[(size_t)EE*EE];
__device__ __nv_bfloat16 g_woh[(size_t)EE*EE], g_wol[(size_t)EE*EE];

__device__ __forceinline__ u32 smem_u32(const void* p) {
    u32 a;
    asm("{ .reg .u64 t; cvta.to.shared.u64 t, %1; cvt.u32.u64 %0, t; }"
        : "=r"(a) : "l"(p));
    return a;
}

#define CP_ASYNC16(saddr, gptr) \
    asm volatile("cp.async.cg.shared.global [%0], [%1], 16;" \
                 :: "r"(saddr), "l"(gptr) : "memory")
#define CP_COMMIT() asm volatile("cp.async.commit_group;" ::: "memory")
#define CP_WAIT1()  asm volatile("cp.async.wait_group 1;" ::: "memory")

__device__ __forceinline__ void ldsm4(u32 addr, u32* r) {
    asm volatile("ldmatrix.sync.aligned.m8n8.x4.shared.b16 {%0,%1,%2,%3}, [%4];"
                 : "=r"(r[0]), "=r"(r[1]), "=r"(r[2]), "=r"(r[3]) : "r"(addr));
}
__device__ __forceinline__ void mma16816(float* c, const u32* a, const u32* b) {
    asm volatile(
        "mma.sync.aligned.m16n8k16.row.col.f32.bf16.bf16.f32 "
        "{%0,%1,%2,%3}, {%4,%5,%6,%7}, {%8,%9}, {%0,%1,%2,%3};"
        : "+f"(c[0]), "+f"(c[1]), "+f"(c[2]), "+f"(c[3])
        : "r"(a[0]), "r"(a[1]), "r"(a[2]), "r"(a[3]), "r"(b[0]), "r"(b[1]));
}

// ───────── fp32 → bf16 hi/lo split ─────────
__global__ __launch_bounds__(256) void split_kernel(
    const float* __restrict__ s, __nv_bfloat16* __restrict__ h,
    __nv_bfloat16* __restrict__ l, int n4)
{
    int i = blockIdx.x * blockDim.x + threadIdx.x;
    if (i >= n4) return;
    float4 v = ((const float4*)s)[i];
    float f[4] = {v.x, v.y, v.z, v.w};
    ushort4 ho, lo;
    unsigned short* hp = &ho.x; unsigned short* lp = &lo.x;
    #pragma unroll
    for (int j = 0; j < 4; j++) {
        __nv_bfloat16 hb = __float2bfloat16(f[j]);
        __nv_bfloat16 lb = __float2bfloat16(f[j] - __bfloat162float(hb));
        hp[j] = __bfloat16_as_ushort(hb);
        lp[j] = __bfloat16_as_ushort(lb);
    }
    ((ushort4*)h)[i] = ho;
    ((ushort4*)l)[i] = lo;
}

// ───────── split-bf16 GEMM on mma.sync (HMMA) ─────────
// C[M,N] = A[M,K]·W[N,K]^T + bias  via  Ah·Bh + Ah·Bl + Al·Bh, fp32 accum.
// CTA tile 128×128, 8 warps × (32m × 64n), K-chunk 32, 3-stage cp.async.
#define STG 3
#define CHK 32                 /* halves of K per chunk */
#define ROWB 80                /* padded row pitch in bytes (40 halves) */
#define OPB (128*ROWB)         /* one operand tile: 10240 B */
#define STB (4*OPB)            /* stage: Ah,Al,Bh,Bl = 40960 B */
#define GSMEM (STG*STB)        /* 122880 B */

__global__ __launch_bounds__(256, 1) void bgemm(
    const __nv_bfloat16* __restrict__ Ah, const __nv_bfloat16* __restrict__ Al,
    const __nv_bfloat16* __restrict__ Bh, const __nv_bfloat16* __restrict__ Bl,
    const float* __restrict__ bias, float* __restrict__ C,
    int M, int N_, int K)
{
    extern __shared__ __align__(128) char smem[];
    const u32 sb   = smem_u32(smem);
    const int tid  = threadIdx.x;
    const int wid  = tid >> 5;
    const int lane = tid & 31;
    const int m0   = blockIdx.y * 128;
    const int n0   = blockIdx.x * 128;
    const int wm   = (wid & 3) * 32;
    const int wn   = (wid >> 2) * 64;
    const int nch  = K / CHK;

    const __nv_bfloat16* gsrc[4] = {Ah, Al, Bh, Bl};
    const int rowbase[4] = {m0, m0, n0, n0};

    float acc[2][8][4];
    #pragma unroll
    for (int i = 0; i < 2; i++)
        #pragma unroll
        for (int j = 0; j < 8; j++)
            #pragma unroll
            for (int t = 0; t < 4; t++) acc[i][j][t] = 0.f;

    // issue stage load for chunk c
    auto issue = [&](int c) {
        const u32 s0 = sb + (c % STG) * STB;
        #pragma unroll
        for (int o = 0; o < 4; o++) {
            #pragma unroll
            for (int i = 0; i < 2; i++) {
                int f   = tid + i * 256;          // 0..511
                int row = f >> 2, c4 = f & 3;
                const __nv_bfloat16* g = gsrc[o] +
                    (size_t)(rowbase[o] + row) * K + c * CHK + c4 * 8;
                u32 sa = s0 + o * OPB + row * ROWB + c4 * 16;
                CP_ASYNC16(sa, g);
            }
        }
        CP_COMMIT();
    };

    issue(0);
    issue(1);

    for (int c = 0; c < nch; c++) {
        CP_WAIT1();
        __syncthreads();
        if (c + 2 < nch) issue(c + 2); else CP_COMMIT();

        const u32 s0 = sb + (c % STG) * STB;
        #pragma unroll
        for (int ks = 0; ks < 2; ks++) {
            const int k0 = ks * 16;
            u32 ah[2][4], al[2][4], bh[4][4], bl[4][4];
            #pragma unroll
            for (int ma = 0; ma < 2; ma++) {
                int row = wm + ma * 16 + ((lane >> 3) & 1) * 8 + (lane & 7);
                int col = k0 + (lane >> 4) * 8;
                u32 a = s0 + row * ROWB + col * 2;       // Ah at op 0
                ldsm4(a, ah[ma]);
                ldsm4(a + OPB, al[ma]);                  // Al at op 1
            }
            #pragma unroll
            for (int nb = 0; nb < 4; nb++) {
                int row = wn + nb * 16 + (lane >> 4) * 8 + (lane & 7);
                int col = k0 + ((lane >> 3) & 1) * 8;
                u32 b = s0 + 2 * OPB + row * ROWB + col * 2;   // Bh at op 2
                ldsm4(b, bh[nb]);
                ldsm4(b + OPB, bl[nb]);                  // Bl at op 3
            }
            #pragma unroll
            for (int ma = 0; ma < 2; ma++)
                #pragma unroll
                for (int nb = 0; nb < 4; nb++) {
                    mma16816(acc[ma][nb*2+0], ah[ma], &bh[nb][0]);
                    mma16816(acc[ma][nb*2+1], ah[ma], &bh[nb][2]);
                    mma16816(acc[ma][nb*2+0], ah[ma], &bl[nb][0]);
                    mma16816(acc[ma][nb*2+1], ah[ma], &bl[nb][2]);
                    mma16816(acc[ma][nb*2+0], al[ma], &bh[nb][0]);
                    mma16816(acc[ma][nb*2+1], al[ma], &bh[nb][2]);
                }
        }
        __syncthreads();
    }

    // epilogue: c-frag mapping (m = base + lane/4 [+8], n = base + (lane%3)*2)
    #pragma unroll
    for (int ma = 0; ma < 2; ma++) {
        #pragma unroll
        for (int na = 0; na < 8; na++) {
            int row = m0 + wm + ma * 16 + (lane >> 2);
            int col = n0 + wn + na * 8 + (lane & 3) * 2;
            float b0 = bias[col], b1 = bias[col + 1];
            float* p = C + (size_t)row * N_ + col;
            float2 v0 = make_float2(acc[ma][na][0] + b0, acc[ma][na][1] + b1);
            float2 v1 = make_float2(acc[ma][na][2] + b0, acc[ma][na][3] + b1);
            *(float2*)p = v0;
            *(float2*)(p + 8 * (size_t)N_) = v1;
        }
    }
}

// ───────── per-token 16×16 attention + softmax + q-sum + shuffle ─────────
__global__ __launch_bounds__(256) void attn_kernel(
    const float* __restrict__ qb, const float* __restrict__ kb,
    const float* __restrict__ vb, float* __restrict__ z)
{
    __shared__ float sk[HH][DD + 1];
    __shared__ float sv[HH][DD + 1];
    __shared__ float sq[HH][DD + 1];
    __shared__ float ss[HH][HH + 1];
    __shared__ float sp_[HH][HH + 1];

    const int n   = blockIdx.x;
    const int b   = n >> 11;
    const int sp  = n & 2047;
    const int tid = threadIdx.x;

    for (int i = tid; i < EE; i += 256) {
        sk[i >> 6][i & 63] = kb[(size_t)n * EE + i];
        sv[i >> 6][i & 63] = vb[(size_t)n * EE + i];
    }

    const int d  = tid & 63;
    const int hq = tid >> 6;
    const int sh = tid >> 4;
    const int sg = tid & 15;
    const float scale = 0.125f;

    float acc[4] = {0.f, 0.f, 0.f, 0.f};

    for (int qi = 0; qi < QQ; qi++) {
        for (int i = tid; i < EE; i += 256)
            sq[i >> 6][i & 63] = qb[(size_t)n * (QQ * EE) + qi * EE + i];
        __syncthreads();

        float s = 0.f;
        #pragma unroll
        for (int dd = 0; dd < DD; dd++) s += sq[sh][dd] * sk[sg][dd];
        ss[sh][sg] = s * scale;
        __syncthreads();

        if (tid < HH) {
            float m = -1e30f;
            #pragma unroll
            for (int g = 0; g < HH; g++) m = fmaxf(m, ss[tid][g]);
            float e[HH], sum = 0.f;
            #pragma unroll
            for (int g = 0; g < HH; g++) { e[g] = __expf(ss[tid][g] - m); sum += e[g]; }
            float inv = 1.f / sum;
            #pragma unroll
            for (int g = 0; g < HH; g++) sp_[tid][g] = e[g] * inv;
        }
        __syncthreads();

        #pragma unroll
        for (int j = 0; j < 4; j++) {
            int h = hq * 4 + j;
            float o = 0.f;
            #pragma unroll
            for (int g = 0; g < HH; g++) o += sp_[h][g] * sv[g][d];
            acc[j] += o;
        }
        __syncthreads();
    }

    #pragma unroll
    for (int j = 0; j < 4; j++) {
        int h    = hq * 4 + j;
        int sfin = h * 128 + (sp >> 4);
        int e    = ((sp & 15) << 6) + d;
        z[((size_t)b * SS + sfin) * EE + e] = acc[j];
    }
}

// ───────── launch ─────────
extern "C" void kernel_launch(void* const* d_in, const int* in_sizes, int n_in,
                              void* d_out, int out_size)
{
    const float* x  = (const float*)d_in[0];
    const float* Wq = (const float*)d_in[1];
    const float* bq = (const float*)d_in[2];
    const float* Wk = (const float*)d_in[3];
    const float* bk = (const float*)d_in[4];
    const float* Wv = (const float*)d_in[5];
    const float* bv = (const float*)d_in[6];
    const float* Wo = (const float*)d_in[7];
    const float* bo = (const float*)d_in[8];
    float* out = (float*)d_out;

    float *pq, *pk, *pv, *pz;
    __nv_bfloat16 *xh, *xl, *zh, *zl, *wqh, *wql, *wkh, *wkl, *wvh, *wvl, *woh, *wol;
    cudaGetSymbolAddress((void**)&pq, g_q);
    cudaGetSymbolAddress((void**)&pk, g_k);
    cudaGetSymbolAddress((void**)&pv, g_v);
    cudaGetSymbolAddress((void**)&pz, g_z);
    cudaGetSymbolAddress((void**)&xh, g_xh);  cudaGetSymbolAddress((void**)&xl, g_xl);
    cudaGetSymbolAddress((void**)&zh, g_zh);  cudaGetSymbolAddress((void**)&zl, g_zl);
    cudaGetSymbolAddress((void**)&wqh, g_wqh); cudaGetSymbolAddress((void**)&wql, g_wql);
    cudaGetSymbolAddress((void**)&wkh, g_wkh); cudaGetSymbolAddress((void**)&wkl, g_wkl);
    cudaGetSymbolAddress((void**)&wvh, g_wvh); cudaGetSymbolAddress((void**)&wvl, g_wvl);
    cudaGetSymbolAddress((void**)&woh, g_woh); cudaGetSymbolAddress((void**)&wol, g_wol);

    cudaFuncSetAttribute(bgemm, cudaFuncAttributeMaxDynamicSharedMemorySize, GSMEM);

    dim3 blk(256);
    split_kernel<<<(MM*EE/4 + 255)/256, blk>>>(x,  xh,  xl,  MM*EE/4);
    split_kernel<<<(QQ*EE*EE/4 + 255)/256, blk>>>(Wq, wqh, wql, QQ*EE*EE/4);
    split_kernel<<<(EE*EE/4 + 255)/256, blk>>>(Wk, wkh, wkl, EE*EE/4);
    split_kernel<<<(EE*EE/4 + 255)/256, blk>>>(Wv, wvh, wvl, EE*EE/4);
    split_kernel<<<(EE*EE/4 + 255)/256, blk>>>(Wo, woh, wol, EE*EE/4);

    bgemm<<<dim3(QQ*EE/128, MM/128), blk, GSMEM>>>(xh, xl, wqh, wql, bq, pq, MM, QQ*EE, EE);
    bgemm<<<dim3(EE/128,    MM/128), blk, GSMEM>>>(xh, xl, wkh, wkl, bk, pk, MM, EE, EE);
    bgemm<<<dim3(EE/128,    MM/128), blk, GSMEM>>>(xh, xl, wvh, wvl, bv, pv, MM, EE, EE);

    attn_kernel<<<MM, blk>>>(pq, pk, pv, pz);
    split_kernel<<<(MM*EE/4 + 255)/256, blk>>>(pz, zh, zl, MM*EE/4);
    bgemm<<<dim3(EE/128, MM/128), blk, GSMEM>>>(zh, zl, woh, wol, bo, out, MM, EE, EE);
}

// round 4
// speedup vs baseline: 2.5153x; 1.2096x over previous
#include <cuda_runtime.h>
#include <cuda_bf16.h>

typedef unsigned int u32;
typedef unsigned long long u64;

#define BB 4
#define SS 2048
#define EE 1024
#define HH 16
#define DD 64
#define QQ 4
#define MM (BB*SS)   /* 8192 tokens */

// ───────── scratch (allocation-free rule: __device__ globals) ─────────
__device__ float g_q[(size_t)MM * (QQ*EE)];
__device__ float g_k[(size_t)MM * EE];
__device__ float g_v[(size_t)MM * EE];
__device__ float g_z[(size_t)MM * EE];

__device__ __nv_bfloat16 g_xh[(size_t)MM*EE],  g_xl[(size_t)MM*EE];
__device__ __nv_bfloat16 g_zh[(size_t)MM*EE],  g_zl[(size_t)MM*EE];
__device__ __nv_bfloat16 g_wqh[(size_t)QQ*EE*EE], g_wql[(size_t)QQ*EE*EE];
__device__ __nv_bfloat16 g_wkh[(size_t)EE*EE], g_wkl[(size_t)EE*EE];
__device__ __nv_bfloat16 g_wvh[(size_t)EE*EE], g_wvl[(size_t)EE*EE];
__device__ __nv_bfloat16 g_woh[(size_t)EE*EE], g_wol[(size_t)EE*EE];

__device__ __forceinline__ u32 smem_u32(const void* p) {
    u32 a;
    asm("{ .reg .u64 t; cvta.to.shared.u64 t, %1; cvt.u32.u64 %0, t; }"
        : "=r"(a) : "l"(p));
    return a;
}

#define CP_ASYNC16(saddr, gptr) \
    asm volatile("cp.async.cg.shared.global [%0], [%1], 16;" \
                 :: "r"(saddr), "l"(gptr) : "memory")
#define CP_COMMIT() asm volatile("cp.async.commit_group;" ::: "memory")
#define CP_WAIT1()  asm volatile("cp.async.wait_group 1;" ::: "memory")

__device__ __forceinline__ void ldsm4(u32 addr, u32* r) {
    asm volatile("ldmatrix.sync.aligned.m8n8.x4.shared.b16 {%0,%1,%2,%3}, [%4];"
                 : "=r"(r[0]), "=r"(r[1]), "=r"(r[2]), "=r"(r[3]) : "r"(addr));
}
__device__ __forceinline__ void mma16816(float* c, const u32* a, const u32* b) {
    asm volatile(
        "mma.sync.aligned.m16n8k16.row.col.f32.bf16.bf16.f32 "
        "{%0,%1,%2,%3}, {%4,%5,%6,%7}, {%8,%9}, {%0,%1,%2,%3};"
        : "+f"(c[0]), "+f"(c[1]), "+f"(c[2]), "+f"(c[3])
        : "r"(a[0]), "r"(a[1]), "r"(a[2]), "r"(a[3]), "r"(b[0]), "r"(b[1]));
}

// ───────── fp32 → bf16 hi/lo split ─────────
__global__ __launch_bounds__(256) void split_kernel(
    const float* __restrict__ s, __nv_bfloat16* __restrict__ h,
    __nv_bfloat16* __restrict__ l, int n4)
{
    int i = blockIdx.x * blockDim.x + threadIdx.x;
    if (i >= n4) return;
    float4 v = ((const float4*)s)[i];
    float f[4] = {v.x, v.y, v.z, v.w};
    ushort4 ho, lo;
    unsigned short* hp = &ho.x; unsigned short* lp = &lo.x;
    #pragma unroll
    for (int j = 0; j < 4; j++) {
        __nv_bfloat16 hb = __float2bfloat16(f[j]);
        __nv_bfloat16 lb = __float2bfloat16(f[j] - __bfloat162float(hb));
        hp[j] = __bfloat16_as_ushort(hb);
        lp[j] = __bfloat16_as_ushort(lb);
    }
    ((ushort4*)h)[i] = ho;
    ((ushort4*)l)[i] = lo;
}

// ───────── split-bf16 GEMM on mma.sync (HMMA) ─────────
// C[M,N] = A[M,K]·W[N,K]^T + bias  via  Ah·Bh + Ah·Bl + Al·Bh, fp32 accum.
// CTA tile 128×256, 8 warps × (64m × 64n), K-chunk 32, 3-stage cp.async,
// one barrier per chunk.
#define STG 3
#define CHK 32
#define ROWB 80
#define AOPB (128*ROWB)
#define BOPB (256*ROWB)
#define SOFF_AH 0
#define SOFF_AL AOPB
#define SOFF_BH (2*AOPB)
#define SOFF_BL (2*AOPB + BOPB)
#define STB (2*AOPB + 2*BOPB)
#define GSMEM (STG*STB)

__global__ __launch_bounds__(256, 1) void bgemm(
    const __nv_bfloat16* __restrict__ Ah, const __nv_bfloat16* __restrict__ Al,
    const __nv_bfloat16* __restrict__ Bh, const __nv_bfloat16* __restrict__ Bl,
    const float* __restrict__ bias, float* __restrict__ C,
    int M, int N_, int K)
{
    extern __shared__ __align__(128) char smem[];
    const u32 sb   = smem_u32(smem);
    const int tid  = threadIdx.x;
    const int wid  = tid >> 5;
    const int lane = tid & 31;
    const int m0   = blockIdx.y * 128;
    const int n0   = blockIdx.x * 256;
    const int wm   = (wid & 1) * 64;
    const int wn   = (wid >> 1) * 64;
    const int nch  = K / CHK;

    float acc[4][8][4];
    #pragma unroll
    for (int i = 0; i < 4; i++)
        #pragma unroll
        for (int j = 0; j < 8; j++)
            #pragma unroll
            for (int t = 0; t < 4; t++) acc[i][j][t] = 0.f;

    auto issue = [&](int c) {
        const u32 s0 = sb + (c % STG) * STB;
        #pragma unroll
        for (int i = 0; i < 2; i++) {
            int f = tid + i * 256;
            int row = f >> 2, c4 = f & 3;
            size_t g = (size_t)(m0 + row) * K + c * CHK + c4 * 8;
            u32 sa = s0 + row * ROWB + c4 * 16;
            CP_ASYNC16(sa + SOFF_AH, Ah + g);
            CP_ASYNC16(sa + SOFF_AL, Al + g);
        }
        #pragma unroll
        for (int i = 0; i < 4; i++) {
            int f = tid + i * 256;
            int row = f >> 2, c4 = f & 3;
            size_t g = (size_t)(n0 + row) * K + c * CHK + c4 * 8;
            u32 sa = s0 + row * ROWB + c4 * 16;
            CP_ASYNC16(sa + SOFF_BH, Bh + g);
            CP_ASYNC16(sa + SOFF_BL, Bl + g);
        }
        CP_COMMIT();
    };

    issue(0);
    issue(1);

    for (int c = 0; c < nch; c++) {
        CP_WAIT1();
        __syncthreads();
        if (c + 2 < nch) issue(c + 2); else CP_COMMIT();

        const u32 s0 = sb + (c % STG) * STB;
        #pragma unroll
        for (int ks = 0; ks < 2; ks++) {
            const int k0 = ks * 16;
            u32 ah[4][4], al[4][4];
            #pragma unroll
            for (int ma = 0; ma < 4; ma++) {
                int row = wm + ma * 16 + ((lane >> 3) & 1) * 8 + (lane & 7);
                int col = k0 + (lane >> 4) * 8;
                u32 a = s0 + row * ROWB + col * 2;
                ldsm4(a + SOFF_AH, ah[ma]);
                ldsm4(a + SOFF_AL, al[ma]);
            }
            // 4 col-blocks of 16 n-cols each; each ldsm4 B fragment yields
            // two n8 mma fragments (&b[0], &b[2]) → 8 acc slots total.
            #pragma unroll
            for (int j = 0; j < 4; j++) {
                u32 bh[4], bl[4];
                int row = wn + j * 16 + (lane >> 4) * 8 + (lane & 7);
                int col = k0 + ((lane >> 3) & 1) * 8;
                u32 bptr = s0 + row * ROWB + col * 2;
                ldsm4(bptr + SOFF_BH, bh);
                ldsm4(bptr + SOFF_BL, bl);
                #pragma unroll
                for (int ma = 0; ma < 4; ma++) {
                    float* c0 = acc[ma][j * 2 + 0];
                    float* c1 = acc[ma][j * 2 + 1];
                    mma16816(c0, ah[ma], &bh[0]);
                    mma16816(c1, ah[ma], &bh[2]);
                    mma16816(c0, ah[ma], &bl[0]);
                    mma16816(c1, ah[ma], &bl[2]);
                    mma16816(c0, al[ma], &bh[0]);
                    mma16816(c1, al[ma], &bh[2]);
                }
            }
        }
    }
    __syncthreads();

    #pragma unroll
    for (int ma = 0; ma < 4; ma++) {
        #pragma unroll
        for (int nb = 0; nb < 8; nb++) {
            int row = m0 + wm + ma * 16 + (lane >> 2);
            int col = n0 + wn + nb * 8 + (lane & 3) * 2;
            float b0 = bias[col], b1 = bias[col + 1];
            float* p = C + (size_t)row * N_ + col;
            *(float2*)p = make_float2(acc[ma][nb][0] + b0, acc[ma][nb][1] + b1);
            *(float2*)(p + 8 * (size_t)N_) =
                make_float2(acc[ma][nb][2] + b0, acc[ma][nb][3] + b1);
        }
    }
}

// ───────── per-token 16×16 attention + softmax + q-sum + shuffle ─────────
__global__ __launch_bounds__(256) void attn_kernel(
    const float* __restrict__ qb, const float* __restrict__ kb,
    const float* __restrict__ vb, float* __restrict__ z)
{
    __shared__ float sk[HH][66];
    __shared__ float sv[HH][66];
    __shared__ float sq[QQ][HH][66];
    __shared__ float ss[QQ*HH][HH + 1];
    __shared__ float sp_[QQ*HH][HH + 1];

    const int n   = blockIdx.x;
    const int b   = n >> 11;
    const int sp  = n & 2047;
    const int tid = threadIdx.x;

    {
        const float4* kv4 = (const float4*)(kb + (size_t)n * EE);
        const float4* vv4 = (const float4*)(vb + (size_t)n * EE);
        int r = tid >> 4, c4 = (tid & 15) * 4;
        float4 kf = kv4[tid], vf = vv4[tid];
        sk[r][c4] = kf.x; sk[r][c4+1] = kf.y; sk[r][c4+2] = kf.z; sk[r][c4+3] = kf.w;
        sv[r][c4] = vf.x; sv[r][c4+1] = vf.y; sv[r][c4+2] = vf.z; sv[r][c4+3] = vf.w;
        const float4* q4 = (const float4*)(qb + (size_t)n * (QQ * EE));
        #pragma unroll
        for (int j = 0; j < 4; j++) {
            int idx = tid + j * 256;
            int qi = idx >> 8, rr = (idx >> 4) & 15, cc = (idx & 15) * 4;
            float4 qf = q4[idx];
            sq[qi][rr][cc]   = qf.x; sq[qi][rr][cc+1] = qf.y;
            sq[qi][rr][cc+2] = qf.z; sq[qi][rr][cc+3] = qf.w;
        }
    }
    __syncthreads();

    {
        const int h = tid >> 4, g = tid & 15;
        const float2* kr = (const float2*)&sk[g][0];
        #pragma unroll
        for (int qi = 0; qi < QQ; qi++) {
            const float2* qr = (const float2*)&sq[qi][h][0];
            float s = 0.f;
            #pragma unroll
            for (int dd = 0; dd < 32; dd++) {
                float2 a = qr[dd], c = kr[dd];
                s += a.x * c.x + a.y * c.y;
            }
            ss[qi * HH + h][g] = s * 0.125f;
        }
    }
    __syncthreads();

    if (tid < QQ * HH) {
        float m = -1e30f;
        #pragma unroll
        for (int g = 0; g < HH; g++) m = fmaxf(m, ss[tid][g]);
        float e[HH], sum = 0.f;
        #pragma unroll
        for (int g = 0; g < HH; g++) { e[g] = __expf(ss[tid][g] - m); sum += e[g]; }
        float inv = 1.f / sum;
        #pragma unroll
        for (int g = 0; g < HH; g++) sp_[tid][g] = e[g] * inv;
    }
    __syncthreads();

    const int d  = tid & 63;
    const int hq = tid >> 6;
    #pragma unroll
    for (int j = 0; j < 4; j++) {
        int h = hq * 4 + j;
        float o = 0.f;
        #pragma unroll
        for (int qi = 0; qi < QQ; qi++) {
            const float* pr = sp_[qi * HH + h];
            #pragma unroll
            for (int g = 0; g < HH; g++) o += pr[g] * sv[g][d];
        }
        int sfin = h * 128 + (sp >> 4);
        int e    = ((sp & 15) << 6) + d;
        z[((size_t)b * SS + sfin) * EE + e] = o;
    }
}

// ───────── launch ─────────
extern "C" void kernel_launch(void* const* d_in, const int* in_sizes, int n_in,
                              void* d_out, int out_size)
{
    const float* x  = (const float*)d_in[0];
    const float* Wq = (const float*)d_in[1];
    const float* bq = (const float*)d_in[2];
    const float* Wk = (const float*)d_in[3];
    const float* bk = (const float*)d_in[4];
    const float* Wv = (const float*)d_in[5];
    const float* bv = (const float*)d_in[6];
    const float* Wo = (const float*)d_in[7];
    const float* bo = (const float*)d_in[8];
    float* out = (float*)d_out;

    float *pq, *pk, *pv, *pz;
    __nv_bfloat16 *xh, *xl, *zh, *zl, *wqh, *wql, *wkh, *wkl, *wvh, *wvl, *woh, *wol;
    cudaGetSymbolAddress((void**)&pq, g_q);
    cudaGetSymbolAddress((void**)&pk, g_k);
    cudaGetSymbolAddress((void**)&pv, g_v);
    cudaGetSymbolAddress((void**)&pz, g_z);
    cudaGetSymbolAddress((void**)&xh, g_xh);  cudaGetSymbolAddress((void**)&xl, g_xl);
    cudaGetSymbolAddress((void**)&zh, g_zh);  cudaGetSymbolAddress((void**)&zl, g_zl);
    cudaGetSymbolAddress((void**)&wqh, g_wqh); cudaGetSymbolAddress((void**)&wql, g_wql);
    cudaGetSymbolAddress((void**)&wkh, g_wkh); cudaGetSymbolAddress((void**)&wkl, g_wkl);
    cudaGetSymbolAddress((void**)&wvh, g_wvh); cudaGetSymbolAddress((void**)&wvl, g_wvl);
    cudaGetSymbolAddress((void**)&woh, g_woh); cudaGetSymbolAddress((void**)&wol, g_wol);

    cudaFuncSetAttribute(bgemm, cudaFuncAttributeMaxDynamicSharedMemorySize, GSMEM);

    dim3 blk(256);
    split_kernel<<<(MM*EE/4 + 255)/256, blk>>>(x,  xh,  xl,  MM*EE/4);
    split_kernel<<<(QQ*EE*EE/4 + 255)/256, blk>>>(Wq, wqh, wql, QQ*EE*EE/4);
    split_kernel<<<(EE*EE/4 + 255)/256, blk>>>(Wk, wkh, wkl, EE*EE/4);
    split_kernel<<<(EE*EE/4 + 255)/256, blk>>>(Wv, wvh, wvl, EE*EE/4);
    split_kernel<<<(EE*EE/4 + 255)/256, blk>>>(Wo, woh, wol, EE*EE/4);

    bgemm<<<dim3(QQ*EE/256, MM/128), blk, GSMEM>>>(xh, xl, wqh, wql, bq, pq, MM, QQ*EE, EE);
    bgemm<<<dim3(EE/256,    MM/128), blk, GSMEM>>>(xh, xl, wkh, wkl, bk, pk, MM, EE, EE);
    bgemm<<<dim3(EE/256,    MM/128), blk, GSMEM>>>(xh, xl, wvh, wvl, bv, pv, MM, EE, EE);

    attn_kernel<<<MM, blk>>>(pq, pk, pv, pz);
    split_kernel<<<(MM*EE/4 + 255)/256, blk>>>(pz, zh, zl, MM*EE/4);
    bgemm<<<dim3(EE/256, MM/128), blk, GSMEM>>>(zh, zl, woh, wol, bo, out, MM, EE, EE);
}

// round 5
// speedup vs baseline: 3.4202x; 1.3597x over previous
#include <cuda_runtime.h>
#include <cuda.h>
#include <cuda_bf16.h>

typedef unsigned int u32;
typedef unsigned long long u64;

#define BB 4
#define SS 2048
#define EE 1024
#define HH 16
#define DD 64
#define QQ 4
#define MM (BB*SS)   /* 8192 tokens */

// ───────── scratch (allocation-free rule: __device__ globals) ─────────
__device__ float g_q[(size_t)MM * (QQ*EE)];
__device__ float g_k[(size_t)MM * EE];
__device__ float g_v[(size_t)MM * EE];

__device__ __nv_bfloat16 g_xh[(size_t)MM*EE],  g_xl[(size_t)MM*EE];
__device__ __nv_bfloat16 g_zh[(size_t)MM*EE],  g_zl[(size_t)MM*EE];
__device__ __nv_bfloat16 g_wqh[(size_t)QQ*EE*EE], g_wql[(size_t)QQ*EE*EE];
__device__ __nv_bfloat16 g_wkh[(size_t)EE*EE], g_wkl[(size_t)EE*EE];
__device__ __nv_bfloat16 g_wvh[(size_t)EE*EE], g_wvl[(size_t)EE*EE];
__device__ __nv_bfloat16 g_woh[(size_t)EE*EE], g_wol[(size_t)EE*EE];

__device__ __forceinline__ u32 smem_u32(const void* p) {
    u32 a;
    asm("{ .reg .u64 t; cvta.to.shared.u64 t, %1; cvt.u32.u64 %0, t; }"
        : "=r"(a) : "l"(p));
    return a;
}

__device__ __forceinline__ void ldsm4(u32 addr, u32* r) {
    asm volatile("ldmatrix.sync.aligned.m8n8.x4.shared.b16 {%0,%1,%2,%3}, [%4];"
                 : "=r"(r[0]), "=r"(r[1]), "=r"(r[2]), "=r"(r[3]) : "r"(addr));
}
__device__ __forceinline__ void mma16816(float* c, const u32* a, const u32* b) {
    asm volatile(
        "mma.sync.aligned.m16n8k16.row.col.f32.bf16.bf16.f32 "
        "{%0,%1,%2,%3}, {%4,%5,%6,%7}, {%8,%9}, {%0,%1,%2,%3};"
        : "+f"(c[0]), "+f"(c[1]), "+f"(c[2]), "+f"(c[3])
        : "r"(a[0]), "r"(a[1]), "r"(a[2]), "r"(a[3]), "r"(b[0]), "r"(b[1]));
}
__device__ __forceinline__ void tma2d(u32 saddr, const CUtensorMap* m,
                                      int cx, int cy, u32 mbar) {
    asm volatile(
        "cp.async.bulk.tensor.2d.shared::cta.global.tile.mbarrier::complete_tx::bytes "
        "[%0], [%1, {%2, %3}], [%4];"
        :: "r"(saddr), "l"(m), "r"(cx), "r"(cy), "r"(mbar) : "memory");
}
#define MBAR_INIT(addr, cnt) \
    asm volatile("mbarrier.init.shared.b64 [%0], %1;" :: "r"(addr), "r"(cnt) : "memory")
#define MBAR_EXPECT(addr, bytes) \
    asm volatile("mbarrier.arrive.expect_tx.shared.b64 _, [%0], %1;" \
                 :: "r"(addr), "r"(bytes) : "memory")
__device__ __forceinline__ void mbar_wait(u32 addr, u32 parity) {
    asm volatile(
        "{\n\t.reg .pred P;\n\t"
        "W%=:\n\t"
        "mbarrier.try_wait.parity.acquire.cta.shared::cta.b64 P, [%0], %1, 0x989680;\n\t"
        "@P bra D%=;\n\t"
        "bra W%=;\n\t"
        "D%=:\n\t}"
        :: "r"(addr), "r"(parity) : "memory");
}
#define SWZ(off) ((u32)(off) ^ ((((u32)(off)) >> 3) & 0x70))

// ───────── fp32 → bf16 hi/lo split ─────────
__global__ __launch_bounds__(256) void split_kernel(
    const float* __restrict__ s, __nv_bfloat16* __restrict__ h,
    __nv_bfloat16* __restrict__ l, int n4)
{
    int i = blockIdx.x * blockDim.x + threadIdx.x;
    if (i >= n4) return;
    float4 v = ((const float4*)s)[i];
    float f[4] = {v.x, v.y, v.z, v.w};
    ushort4 ho, lo;
    unsigned short* hp = &ho.x; unsigned short* lp = &lo.x;
    #pragma unroll
    for (int j = 0; j < 4; j++) {
        __nv_bfloat16 hb = __float2bfloat16(f[j]);
        __nv_bfloat16 lb = __float2bfloat16(f[j] - __bfloat162float(hb));
        hp[j] = __bfloat16_as_ushort(hb);
        lp[j] = __bfloat16_as_ushort(lb);
    }
    ((ushort4*)h)[i] = ho;
    ((ushort4*)l)[i] = lo;
}

// ───────── split-bf16 GEMM: TMA loads + mma.sync ─────────
// C[M,N] = A[M,K]·W[N,K]^T + bias via Ah·Bh + Ah·Bl + Al·Bh, fp32 accum.
// CTA tile 128×256, 8 warps × (64m×64n), K-chunk 64 (128B rows, SW128),
// 2-stage TMA pipeline, mbarrier parity sync.
#define CHK 64
#define SOFF_AH 0u
#define SOFF_AL 16384u
#define SOFF_BH 32768u
#define SOFF_BL 65536u
#define STB 98304u                /* 96 KB per stage */
#define SM_CTRL (2u*STB)          /* mbar[2] */
#define GSMEM (2*98304 + 64)

__global__ __launch_bounds__(256, 1) void bgemm(
    const __grid_constant__ CUtensorMap tAh,
    const __grid_constant__ CUtensorMap tAl,
    const __grid_constant__ CUtensorMap tBh,
    const __grid_constant__ CUtensorMap tBl,
    const float* __restrict__ bias, float* __restrict__ C,
    int M, int N_, int K)
{
    extern __shared__ __align__(1024) char smem[];
    const u32 sb   = smem_u32(smem);
    const int tid  = threadIdx.x;
    const int wid  = tid >> 5;
    const int lane = tid & 31;
    const int m0   = blockIdx.y * 128;
    const int n0   = blockIdx.x * 256;
    const int wm   = (wid & 1) * 64;
    const int wn   = (wid >> 1) * 64;
    const int nch  = K / CHK;         // 16

    float acc[4][8][4];
    #pragma unroll
    for (int i = 0; i < 4; i++)
        #pragma unroll
        for (int j = 0; j < 8; j++)
            #pragma unroll
            for (int t = 0; t < 4; t++) acc[i][j][t] = 0.f;

    if (tid == 0) { MBAR_INIT(sb + SM_CTRL, 1); MBAR_INIT(sb + SM_CTRL + 8, 1); }
    __syncthreads();

    auto issue = [&](int c) {
        if (tid == 0) {
            const u32 mbar = sb + SM_CTRL + (c & 1) * 8;
            const u32 s0   = sb + (c & 1) * STB;
            MBAR_EXPECT(mbar, 98304u);
            int kc = c * CHK;
            tma2d(s0 + SOFF_AH, &tAh, kc, m0, mbar);
            tma2d(s0 + SOFF_AL, &tAl, kc, m0, mbar);
            tma2d(s0 + SOFF_BH, &tBh, kc, n0, mbar);
            tma2d(s0 + SOFF_BL, &tBl, kc, n0, mbar);
        }
    };

    issue(0);
    issue(1);

    for (int c = 0; c < nch; c++) {
        mbar_wait(sb + SM_CTRL + (c & 1) * 8, (c >> 1) & 1);
        const u32 s0 = sb + (c & 1) * STB;

        #pragma unroll
        for (int ks = 0; ks < 4; ks++) {
            const int k0 = ks * 16;
            u32 ah[4][4], al[4][4];
            #pragma unroll
            for (int ma = 0; ma < 4; ma++) {
                int row  = wm + ma * 16 + ((lane >> 3) & 1) * 8 + (lane & 7);
                int colB = (k0 + (lane >> 4) * 8) * 2;
                u32 off  = SWZ(row * 128 + colB);
                ldsm4(s0 + SOFF_AH + off, ah[ma]);
                ldsm4(s0 + SOFF_AL + off, al[ma]);
            }
            #pragma unroll
            for (int j = 0; j < 4; j++) {
                u32 bh[4], bl[4];
                int row  = wn + j * 16 + (lane >> 4) * 8 + (lane & 7);
                int colB = (k0 + ((lane >> 3) & 1) * 8) * 2;
                u32 off  = SWZ(row * 128 + colB);
                ldsm4(s0 + SOFF_BH + off, bh);
                ldsm4(s0 + SOFF_BL + off, bl);
                #pragma unroll
                for (int ma = 0; ma < 4; ma++) {
                    float* c0 = acc[ma][j * 2 + 0];
                    float* c1 = acc[ma][j * 2 + 1];
                    mma16816(c0, ah[ma], &bh[0]);
                    mma16816(c1, ah[ma], &bh[2]);
                    mma16816(c0, ah[ma], &bl[0]);
                    mma16816(c1, ah[ma], &bl[2]);
                    mma16816(c0, al[ma], &bh[0]);
                    mma16816(c1, al[ma], &bh[2]);
                }
            }
        }
        __syncthreads();               // all warps done reading stage (c&1)
        if (c + 2 < nch) issue(c + 2);
    }

    #pragma unroll
    for (int ma = 0; ma < 4; ma++) {
        #pragma unroll
        for (int nb = 0; nb < 8; nb++) {
            int row = m0 + wm + ma * 16 + (lane >> 2);
            int col = n0 + wn + nb * 8 + (lane & 3) * 2;
            float b0 = bias[col], b1 = bias[col + 1];
            float* p = C + (size_t)row * N_ + col;
            *(float2*)p = make_float2(acc[ma][nb][0] + b0, acc[ma][nb][1] + b1);
            *(float2*)(p + 8 * (size_t)N_) =
                make_float2(acc[ma][nb][2] + b0, acc[ma][nb][3] + b1);
        }
    }
}

// ───────── per-token 16×16 attention + softmax + q-sum + shuffle ─────────
// writes bf16 hi/lo directly (feeds the O-projection GEMM).
__global__ __launch_bounds__(256) void attn_kernel(
    const float* __restrict__ qb, const float* __restrict__ kb,
    const float* __restrict__ vb,
    __nv_bfloat16* __restrict__ zh, __nv_bfloat16* __restrict__ zl)
{
    __shared__ float sk[HH][66];
    __shared__ float sv[HH][66];
    __shared__ float sq[QQ][HH][66];
    __shared__ float ss[QQ*HH][HH + 1];
    __shared__ float sp_[QQ*HH][HH + 1];

    const int n   = blockIdx.x;
    const int b   = n >> 11;
    const int sp  = n & 2047;
    const int tid = threadIdx.x;

    {
        const float4* kv4 = (const float4*)(kb + (size_t)n * EE);
        const float4* vv4 = (const float4*)(vb + (size_t)n * EE);
        int r = tid >> 4, c4 = (tid & 15) * 4;
        float4 kf = kv4[tid], vf = vv4[tid];
        sk[r][c4] = kf.x; sk[r][c4+1] = kf.y; sk[r][c4+2] = kf.z; sk[r][c4+3] = kf.w;
        sv[r][c4] = vf.x; sv[r][c4+1] = vf.y; sv[r][c4+2] = vf.z; sv[r][c4+3] = vf.w;
        const float4* q4 = (const float4*)(qb + (size_t)n * (QQ * EE));
        #pragma unroll
        for (int j = 0; j < 4; j++) {
            int idx = tid + j * 256;
            int qi = idx >> 8, rr = (idx >> 4) & 15, cc = (idx & 15) * 4;
            float4 qf = q4[idx];
            sq[qi][rr][cc]   = qf.x; sq[qi][rr][cc+1] = qf.y;
            sq[qi][rr][cc+2] = qf.z; sq[qi][rr][cc+3] = qf.w;
        }
    }
    __syncthreads();

    {
        const int h = tid >> 4, g = tid & 15;
        const float2* kr = (const float2*)&sk[g][0];
        #pragma unroll
        for (int qi = 0; qi < QQ; qi++) {
            const float2* qr = (const float2*)&sq[qi][h][0];
            float s = 0.f;
            #pragma unroll
            for (int dd = 0; dd < 32; dd++) {
                float2 a = qr[dd], c = kr[dd];
                s += a.x * c.x + a.y * c.y;
            }
            ss[qi * HH + h][g] = s * 0.125f;
        }
    }
    __syncthreads();

    if (tid < QQ * HH) {
        float m = -1e30f;
        #pragma unroll
        for (int g = 0; g < HH; g++) m = fmaxf(m, ss[tid][g]);
        float e[HH], sum = 0.f;
        #pragma unroll
        for (int g = 0; g < HH; g++) { e[g] = __expf(ss[tid][g] - m); sum += e[g]; }
        float inv = 1.f / sum;
        #pragma unroll
        for (int g = 0; g < HH; g++) sp_[tid][g] = e[g] * inv;
    }
    __syncthreads();

    const int d  = tid & 63;
    const int hq = tid >> 6;
    #pragma unroll
    for (int j = 0; j < 4; j++) {
        int h = hq * 4 + j;
        float o = 0.f;
        #pragma unroll
        for (int qi = 0; qi < QQ; qi++) {
            const float* pr = sp_[qi * HH + h];
            #pragma unroll
            for (int g = 0; g < HH; g++) o += pr[g] * sv[g][d];
        }
        int sfin = h * 128 + (sp >> 4);
        int e    = ((sp & 15) << 6) + d;
        size_t idx = ((size_t)b * SS + sfin) * EE + e;
        __nv_bfloat16 hb = __float2bfloat16(o);
        zh[idx] = hb;
        zl[idx] = __float2bfloat16(o - __bfloat162float(hb));
    }
}

// ───────── host: TMA descriptor builder ─────────
typedef CUresult (*PFN_encode)(
    CUtensorMap*, CUtensorMapDataType, cuuint32_t, void*,
    const cuuint64_t*, const cuuint64_t*, const cuuint32_t*, const cuuint32_t*,
    CUtensorMapInterleave, CUtensorMapSwizzle, CUtensorMapL2promotion,
    CUtensorMapFloatOOBfill);

static CUtensorMap mk_map(PFN_encode enc, void* base, u64 rows, u32 boxrows) {
    CUtensorMap m;
    cuuint64_t dims[2]    = {(cuuint64_t)EE, rows};
    cuuint64_t strides[1] = {(cuuint64_t)EE * 2};
    cuuint32_t box[2]     = {64u, boxrows};
    cuuint32_t es[2]      = {1u, 1u};
    enc(&m, CU_TENSOR_MAP_DATA_TYPE_BFLOAT16, 2, base, dims, strides, box, es,
        CU_TENSOR_MAP_INTERLEAVE_NONE, CU_TENSOR_MAP_SWIZZLE_128B,
        CU_TENSOR_MAP_L2_PROMOTION_L2_128B, CU_TENSOR_MAP_FLOAT_OOB_FILL_NONE);
    return m;
}

extern "C" void kernel_launch(void* const* d_in, const int* in_sizes, int n_in,
                              void* d_out, int out_size)
{
    const float* x  = (const float*)d_in[0];
    const float* Wq = (const float*)d_in[1];
    const float* bq = (const float*)d_in[2];
    const float* Wk = (const float*)d_in[3];
    const float* bk = (const float*)d_in[4];
    const float* Wv = (const float*)d_in[5];
    const float* bv = (const float*)d_in[6];
    const float* Wo = (const float*)d_in[7];
    const float* bo = (const float*)d_in[8];
    float* out = (float*)d_out;

    float *pq, *pk, *pv;
    __nv_bfloat16 *xh, *xl, *zh, *zl, *wqh, *wql, *wkh, *wkl, *wvh, *wvl, *woh, *wol;
    cudaGetSymbolAddress((void**)&pq, g_q);
    cudaGetSymbolAddress((void**)&pk, g_k);
    cudaGetSymbolAddress((void**)&pv, g_v);
    cudaGetSymbolAddress((void**)&xh, g_xh);  cudaGetSymbolAddress((void**)&xl, g_xl);
    cudaGetSymbolAddress((void**)&zh, g_zh);  cudaGetSymbolAddress((void**)&zl, g_zl);
    cudaGetSymbolAddress((void**)&wqh, g_wqh); cudaGetSymbolAddress((void**)&wql, g_wql);
    cudaGetSymbolAddress((void**)&wkh, g_wkh); cudaGetSymbolAddress((void**)&wkl, g_wkl);
    cudaGetSymbolAddress((void**)&wvh, g_wvh); cudaGetSymbolAddress((void**)&wvl, g_wvl);
    cudaGetSymbolAddress((void**)&woh, g_woh); cudaGetSymbolAddress((void**)&wol, g_wol);

    PFN_encode enc = 0;
    cudaDriverEntryPointQueryResult qr;
    cudaGetDriverEntryPoint("cuTensorMapEncodeTiled", (void**)&enc,
                            cudaEnableDefault, &qr);

    // A-side maps (box 64×128)
    CUtensorMap mXh = mk_map(enc, xh, MM, 128);
    CUtensorMap mXl = mk_map(enc, xl, MM, 128);
    CUtensorMap mZh = mk_map(enc, zh, MM, 128);
    CUtensorMap mZl = mk_map(enc, zl, MM, 128);
    // B-side maps (box 64×256)
    CUtensorMap mQh = mk_map(enc, wqh, (u64)QQ * EE, 256);
    CUtensorMap mQl = mk_map(enc, wql, (u64)QQ * EE, 256);
    CUtensorMap mKh = mk_map(enc, wkh, EE, 256);
    CUtensorMap mKl = mk_map(enc, wkl, EE, 256);
    CUtensorMap mVh = mk_map(enc, wvh, EE, 256);
    CUtensorMap mVl = mk_map(enc, wvl, EE, 256);
    CUtensorMap mOh = mk_map(enc, woh, EE, 256);
    CUtensorMap mOl = mk_map(enc, wol, EE, 256);

    cudaFuncSetAttribute(bgemm, cudaFuncAttributeMaxDynamicSharedMemorySize, GSMEM);

    dim3 blk(256);
    split_kernel<<<(MM*EE/4 + 255)/256, blk>>>(x,  xh,  xl,  MM*EE/4);
    split_kernel<<<(QQ*EE*EE/4 + 255)/256, blk>>>(Wq, wqh, wql, QQ*EE*EE/4);
    split_kernel<<<(EE*EE/4 + 255)/256, blk>>>(Wk, wkh, wkl, EE*EE/4);
    split_kernel<<<(EE*EE/4 + 255)/256, blk>>>(Wv, wvh, wvl, EE*EE/4);
    split_kernel<<<(EE*EE/4 + 255)/256, blk>>>(Wo, woh, wol, EE*EE/4);

    bgemm<<<dim3(QQ*EE/256, MM/128), blk, GSMEM>>>(mXh, mXl, mQh, mQl, bq, pq, MM, QQ*EE, EE);
    bgemm<<<dim3(EE/256,    MM/128), blk, GSMEM>>>(mXh, mXl, mKh, mKl, bk, pk, MM, EE, EE);
    bgemm<<<dim3(EE/256,    MM/128), blk, GSMEM>>>(mXh, mXl, mVh, mVl, bv, pv, MM, EE, EE);

    attn_kernel<<<MM, blk>>>(pq, pk, pv, zh, zl);

    bgemm<<<dim3(EE/256, MM/128), blk, GSMEM>>>(mZh, mZl, mOh, mOl, bo, out, MM, EE, EE);
}